// round 2
// baseline (speedup 1.0000x reference)
#include <cuda_runtime.h>
#include <cuda_bf16.h>
#include <math.h>

// Problem constants
#define T_ 2048
#define B_ 2
#define D_ 768
#define H_ 8
#define HD_ 96
#define FFN_ 3072
#define NR_ (T_ * B_)          // 4096 rows
#define BH_ (B_ * H_)          // 16 attention batches

// ---------------- scratch (__device__ globals; no allocation allowed) ----------------
__device__ float g_q[NR_ * D_];
__device__ float g_k[NR_ * D_];
__device__ float g_v[NR_ * D_];
__device__ float g_scores[(long)BH_ * T_ * T_];   // 268 MB
__device__ float g_attn[NR_ * D_];
__device__ float g_tmp1[NR_ * D_];
__device__ float g_x1[NR_ * D_];
__device__ float g_h1[NR_ * FFN_];
__device__ float g_y[NR_ * D_];

// ---------------- generic tiled GEMM ----------------
// C[M,N] = alpha * A[M,K] @ B + bias + relu + residual
// TRANS_B=true : B is [N,K] row-major (ldb = row stride)   -> C = A @ B^T
// TRANS_B=false: B is [K,N] row-major (ldb = row stride)   -> C = A @ B
// Batched via blockIdx.z: z -> (zb = z/Hh, zh = z%Hh); pointer offsets
// offX1*zb + offX2*zh applied to A, B, C (and residual, same as C).
template<bool TRANS_B>
__global__ void gemm_kernel(const float* __restrict__ A,
                            const float* __restrict__ Bm,
                            const float* __restrict__ bias,
                            const float* __restrict__ residual,
                            float* __restrict__ C,
                            int M, int N, int K,
                            int lda, int ldb, int ldc,
                            long offA1, long offA2,
                            long offB1, long offB2,
                            long offC1, long offC2,
                            int Hh, float alpha, int relu)
{
    int z = blockIdx.z;
    int zb = z / Hh, zh = z % Hh;
    A  += (long)zb * offA1 + (long)zh * offA2;
    Bm += (long)zb * offB1 + (long)zh * offB2;
    C  += (long)zb * offC1 + (long)zh * offC2;
    if (residual) residual += (long)zb * offC1 + (long)zh * offC2;

    __shared__ float As[16][64];
    __shared__ float Bs[16][64];

    const int tid = threadIdx.x;
    const int ty = tid >> 4;       // 0..15 -> row group of 4
    const int tx = tid & 15;       // 0..15 -> col group of 4
    const int rowBase = blockIdx.y * 64;
    const int colBase = blockIdx.x * 64;

    float acc[4][4];
#pragma unroll
    for (int i = 0; i < 4; i++)
#pragma unroll
        for (int j = 0; j < 4; j++) acc[i][j] = 0.f;

    for (int k0 = 0; k0 < K; k0 += 16) {
        // ---- load A tile: As[k][m]
        {
            int mL = tid >> 2;            // 0..63
            int kq = (tid & 3) * 4;       // 0,4,8,12
            int gm = rowBase + mL;
#pragma unroll
            for (int i = 0; i < 4; i++) {
                int gk = k0 + kq + i;
                As[kq + i][mL] = (gm < M && gk < K) ? A[(long)gm * lda + gk] : 0.f;
            }
        }
        // ---- load B tile: Bs[k][n]
        if (TRANS_B) {
            int nL = tid >> 2;
            int kq = (tid & 3) * 4;
            int gn = colBase + nL;
#pragma unroll
            for (int i = 0; i < 4; i++) {
                int gk = k0 + kq + i;
                Bs[kq + i][nL] = (gn < N && gk < K) ? Bm[(long)gn * ldb + gk] : 0.f;
            }
        } else {
            int kL = (tid >> 6) * 4;      // 0,4,8,12
            int nL = tid & 63;
            int gn = colBase + nL;
#pragma unroll
            for (int i = 0; i < 4; i++) {
                int gk = k0 + kL + i;
                Bs[kL + i][nL] = (gk < K && gn < N) ? Bm[(long)gk * ldb + gn] : 0.f;
            }
        }
        __syncthreads();

#pragma unroll
        for (int kk = 0; kk < 16; kk++) {
            float a0 = As[kk][ty * 4 + 0];
            float a1 = As[kk][ty * 4 + 1];
            float a2 = As[kk][ty * 4 + 2];
            float a3 = As[kk][ty * 4 + 3];
            float b0 = Bs[kk][tx * 4 + 0];
            float b1 = Bs[kk][tx * 4 + 1];
            float b2 = Bs[kk][tx * 4 + 2];
            float b3 = Bs[kk][tx * 4 + 3];
            acc[0][0] += a0 * b0; acc[0][1] += a0 * b1; acc[0][2] += a0 * b2; acc[0][3] += a0 * b3;
            acc[1][0] += a1 * b0; acc[1][1] += a1 * b1; acc[1][2] += a1 * b2; acc[1][3] += a1 * b3;
            acc[2][0] += a2 * b0; acc[2][1] += a2 * b1; acc[2][2] += a2 * b2; acc[2][3] += a2 * b3;
            acc[3][0] += a3 * b0; acc[3][1] += a3 * b1; acc[3][2] += a3 * b2; acc[3][3] += a3 * b3;
        }
        __syncthreads();
    }

    // ---- epilogue
#pragma unroll
    for (int i = 0; i < 4; i++) {
        int gm = rowBase + ty * 4 + i;
        if (gm >= M) continue;
#pragma unroll
        for (int j = 0; j < 4; j++) {
            int gn = colBase + tx * 4 + j;
            if (gn >= N) continue;
            float v = acc[i][j] * alpha;
            if (bias) v += bias[gn];
            if (relu) v = fmaxf(v, 0.f);
            if (residual) v += residual[(long)gm * ldc + gn];
            C[(long)gm * ldc + gn] = v;
        }
    }
}

// ---------------- block reductions ----------------
__device__ __forceinline__ float blockReduceSum(float v) {
    __shared__ float s[8];
#pragma unroll
    for (int o = 16; o > 0; o >>= 1) v += __shfl_xor_sync(0xffffffffu, v, o);
    int w = threadIdx.x >> 5, l = threadIdx.x & 31;
    if (l == 0) s[w] = v;
    __syncthreads();
    if (threadIdx.x < 32) {
        v = (threadIdx.x < 8) ? s[threadIdx.x] : 0.f;
#pragma unroll
        for (int o = 4; o > 0; o >>= 1) v += __shfl_xor_sync(0xffffffffu, v, o);
        if (threadIdx.x == 0) s[0] = v;
    }
    __syncthreads();
    v = s[0];
    __syncthreads();
    return v;
}

__device__ __forceinline__ float blockReduceMax(float v) {
    __shared__ float s[8];
#pragma unroll
    for (int o = 16; o > 0; o >>= 1) v = fmaxf(v, __shfl_xor_sync(0xffffffffu, v, o));
    int w = threadIdx.x >> 5, l = threadIdx.x & 31;
    if (l == 0) s[w] = v;
    __syncthreads();
    if (threadIdx.x < 32) {
        v = (threadIdx.x < 8) ? s[threadIdx.x] : -1e30f;
#pragma unroll
        for (int o = 4; o > 0; o >>= 1) v = fmaxf(v, __shfl_xor_sync(0xffffffffu, v, o));
        if (threadIdx.x == 0) s[0] = v;
    }
    __syncthreads();
    v = s[0];
    __syncthreads();
    return v;
}

// ---------------- softmax over rows of length 2048 (256 thr, 8/thread) ----------------
__global__ void softmax_kernel(float* __restrict__ S) {
    long row = blockIdx.x;
    float* p = S + row * T_;
    int tid = threadIdx.x;
    float vals[8];
    float m = -1e30f;
#pragma unroll
    for (int i = 0; i < 8; i++) {
        vals[i] = p[tid + i * 256];
        m = fmaxf(m, vals[i]);
    }
    m = blockReduceMax(m);
    float sum = 0.f;
#pragma unroll
    for (int i = 0; i < 8; i++) {
        vals[i] = __expf(vals[i] - m);
        sum += vals[i];
    }
    sum = blockReduceSum(sum);
    float inv = 1.f / sum;
#pragma unroll
    for (int i = 0; i < 8; i++) p[tid + i * 256] = vals[i] * inv;
}

// ---------------- layernorm over rows of length 768 (256 thr, 3/thread) ----------------
__global__ void layernorm_kernel(const float* __restrict__ X,
                                 const float* __restrict__ g,
                                 const float* __restrict__ b,
                                 float* __restrict__ Y) {
    long row = blockIdx.x;
    const float* p = X + row * D_;
    float* q = Y + row * D_;
    int tid = threadIdx.x;
    float vals[3];
    float sum = 0.f;
#pragma unroll
    for (int i = 0; i < 3; i++) {
        vals[i] = p[tid + i * 256];
        sum += vals[i];
    }
    float mu = blockReduceSum(sum) * (1.f / D_);
    float vs = 0.f;
#pragma unroll
    for (int i = 0; i < 3; i++) {
        float d = vals[i] - mu;
        vs += d * d;
    }
    float var = blockReduceSum(vs) * (1.f / D_);
    float rs = rsqrtf(var + 1e-5f);
#pragma unroll
    for (int i = 0; i < 3; i++) {
        int c = tid + i * 256;
        q[c] = (vals[i] - mu) * rs * g[c] + b[c];
    }
}

// ---------------- launch ----------------
extern "C" void kernel_launch(void* const* d_in, const int* in_sizes, int n_in,
                              void* d_out, int out_size)
{
    const float* x     = (const float*)d_in[0];
    const float* wq    = (const float*)d_in[1];
    const float* bq    = (const float*)d_in[2];
    const float* wk    = (const float*)d_in[3];
    const float* bk    = (const float*)d_in[4];
    const float* wv    = (const float*)d_in[5];
    const float* bv    = (const float*)d_in[6];
    const float* wo    = (const float*)d_in[7];
    const float* bo    = (const float*)d_in[8];
    const float* ln1g  = (const float*)d_in[9];
    const float* ln1b  = (const float*)d_in[10];
    const float* w1    = (const float*)d_in[11];
    const float* b1    = (const float*)d_in[12];
    const float* w2    = (const float*)d_in[13];
    const float* b2    = (const float*)d_in[14];
    const float* ln2g  = (const float*)d_in[15];
    const float* ln2b  = (const float*)d_in[16];
    float* out = (float*)d_out;

    float *q, *k, *v, *sc, *attn, *tmp1, *x1, *h1, *y;
    cudaGetSymbolAddress((void**)&q,    g_q);
    cudaGetSymbolAddress((void**)&k,    g_k);
    cudaGetSymbolAddress((void**)&v,    g_v);
    cudaGetSymbolAddress((void**)&sc,   g_scores);
    cudaGetSymbolAddress((void**)&attn, g_attn);
    cudaGetSymbolAddress((void**)&tmp1, g_tmp1);
    cudaGetSymbolAddress((void**)&x1,   g_x1);
    cudaGetSymbolAddress((void**)&h1,   g_h1);
    cudaGetSymbolAddress((void**)&y,    g_y);

    const float scale = 0.102062072615966f;  // 1/sqrt(96)
    dim3 blk(256);

    // QKV projections: [4096,768] = x @ W^T + b
    dim3 gProj((D_ + 63) / 64, (NR_ + 63) / 64, 1);
    gemm_kernel<true><<<gProj, blk>>>(x, wq, bq, nullptr, q, NR_, D_, D_,
                                      D_, D_, D_, 0,0,0,0,0,0, 1, 1.f, 0);
    gemm_kernel<true><<<gProj, blk>>>(x, wk, bk, nullptr, k, NR_, D_, D_,
                                      D_, D_, D_, 0,0,0,0,0,0, 1, 1.f, 0);
    gemm_kernel<true><<<gProj, blk>>>(x, wv, bv, nullptr, v, NR_, D_, D_,
                                      D_, D_, D_, 0,0,0,0,0,0, 1, 1.f, 0);

    // scores[z=b*H+h][t][s] = scale * Q_bh @ K_bh^T   (batched, strided views)
    dim3 gScore(T_ / 64, T_ / 64, BH_);
    gemm_kernel<true><<<gScore, blk>>>(q, k, nullptr, nullptr, sc,
                                       T_, T_, HD_,
                                       B_ * D_, B_ * D_, T_,
                                       (long)D_, (long)HD_,
                                       (long)D_, (long)HD_,
                                       (long)H_ * T_ * T_, (long)T_ * T_,
                                       H_, scale, 0);

    // softmax over s
    softmax_kernel<<<(unsigned)((long)BH_ * T_), blk>>>(sc);

    // attn = P @ V (batched; B in [K,N] layout via strided view of v)
    dim3 gPV((HD_ + 63) / 64, T_ / 64, BH_);
    gemm_kernel<false><<<gPV, blk>>>(sc, v, nullptr, nullptr, attn,
                                     T_, HD_, T_,
                                     T_, B_ * D_, B_ * D_,
                                     (long)H_ * T_ * T_, (long)T_ * T_,
                                     (long)D_, (long)HD_,
                                     (long)D_, (long)HD_,
                                     H_, 1.f, 0);

    // O projection + residual(x)
    gemm_kernel<true><<<gProj, blk>>>(attn, wo, bo, x, tmp1, NR_, D_, D_,
                                      D_, D_, D_, 0,0,0,0,0,0, 1, 1.f, 0);

    // LN1
    layernorm_kernel<<<NR_, blk>>>(tmp1, ln1g, ln1b, x1);

    // FFN1: relu(x1 @ w1^T + b1)
    dim3 gF1(FFN_ / 64, NR_ / 64, 1);
    gemm_kernel<true><<<gF1, blk>>>(x1, w1, b1, nullptr, h1, NR_, FFN_, D_,
                                    D_, D_, FFN_, 0,0,0,0,0,0, 1, 1.f, 1);

    // FFN2: h1 @ w2^T + b2 + x1
    gemm_kernel<true><<<gProj, blk>>>(h1, w2, b2, x1, y, NR_, D_, FFN_,
                                      FFN_, FFN_, D_, 0,0,0,0,0,0, 1, 1.f, 0);

    // LN2 -> output
    layernorm_kernel<<<NR_, blk>>>(y, ln2g, ln2b, out);
}